// round 15
// baseline (speedup 1.0000x reference)
#include <cuda_runtime.h>
#include <cstdint>

// ---------------------------------------------------------------------------
// ExpertsChooseMaskedExpand — round 13: k2 on the cp.async engine
//
//   WC : wt  = tf32(weight)                                    (~16 us)
//   CC : cz  = tf32(combine)                                   (~8 us)
//   K1 : xdT[b,e] (512x512, tf32) = x_e^T @ dispatch_e          8.6 GF (old engine)
//   RS : s[b,t] = rowsum(combine)                               tiny
//   K2 : z[b] (1024x2048, tf32)   = cz_e @ xdT_e^T              8.6 GF (cp.async engine)
//   K3 : out[b] (1024x8192)       = z[b] @ wt_seg^T + bias*s  137.4 GF (cp.async engine)
//
// cp.async engine: CTA 128x256, 8 warps (64x64), 3-stage pipeline, K-chunk 32,
// operands pre-converted tf32 bits (raw 16B copies, no cvt in mainloop).
// ---------------------------------------------------------------------------

#define NTHREADS   256
#define BKT        32
#define TILE_BYTES 16384            // 128 rows x 128 B
#define CA_STAGE   49152            // A 16 KB + B 32 KB
#define CA_SMEM    (3 * CA_STAGE + 256)

__device__ float g_xdT[16ull * 512 * 512];    // 16 MB  (b*4+e, i, c) tf32 bits
__device__ float g_cz [4ull * 1024 * 2048];   // 32 MB  combine, tf32 bits
__device__ float g_z  [4ull * 1024 * 2048];   // 32 MB  (b, t, e*512+i) tf32 bits
__device__ float g_wt [8192ull * 2048];       // 64 MB  weight, tf32 bits
__device__ float g_s  [4 * 1024];             // rowsum of combine (f32)

// ---------------------------------------------------------------- helpers --
__device__ __forceinline__ uint32_t smem_u32(const void* p) {
    uint32_t a;
    asm("{ .reg .u64 t; cvta.to.shared.u64 t, %1; cvt.u32.u64 %0, t; }"
        : "=r"(a) : "l"(p));
    return a;
}
__device__ __forceinline__ uint32_t f2tf32(float x) {
    uint32_t r;
    asm("cvt.rna.tf32.f32 %0, %1;" : "=r"(r) : "f"(x));
    return r;
}
__device__ __forceinline__ int swz_off(int row, int byte_in_row) {
    const int c16 = byte_in_row >> 4;
    const int sub = byte_in_row & 15;
    return row * 128 + (((c16 ^ (row & 7)) << 4) | sub);
}
__device__ __forceinline__ uint32_t swz16(int row, int q) {
    return (uint32_t)(row * 128 + ((q ^ (row & 7)) << 4));
}

#define LDSM_X4(r0, r1, r2, r3, addr)                                          \
    asm volatile("ldmatrix.sync.aligned.m8n8.x4.shared.b16 {%0,%1,%2,%3}, [%4];" \
                 : "=r"(r0), "=r"(r1), "=r"(r2), "=r"(r3) : "r"(addr))

#define MMA_TF32(c, a, b0v, b1v)                                               \
    asm volatile("mma.sync.aligned.m16n8k8.row.col.f32.tf32.tf32.f32 "         \
                 "{%0,%1,%2,%3}, {%4,%5,%6,%7}, {%8,%9}, {%0,%1,%2,%3};"       \
                 : "+f"((c)[0]), "+f"((c)[1]), "+f"((c)[2]), "+f"((c)[3])      \
                 : "r"((a)[0]), "r"((a)[1]), "r"((a)[2]), "r"((a)[3]),         \
                   "r"(b0v), "r"(b1v))

#define CP_ASYNC16(dst, src)                                                   \
    asm volatile("cp.async.cg.shared.global [%0], [%1], 16;"                   \
                 :: "r"(dst), "l"(src))
#define CP_COMMIT()  asm volatile("cp.async.commit_group;" ::: "memory")
#define CP_WAIT(n)   asm volatile("cp.async.wait_group %0;" :: "n"(n) : "memory")

// ================= old engine (k1 only) ===================================
template <bool KC>
__device__ __forceinline__ void ldg_tile(const float* __restrict__ S, long ld,
                                         int tid, float v[16]) {
    if (KC) {
        const int q  = tid & 7;
        const int r0 = tid >> 3;
#pragma unroll
        for (int i = 0; i < 4; ++i)
            *(float4*)(v + 4 * i) =
                *(const float4*)(S + (long)(r0 + 32 * i) * ld + q * 4);
    } else {
        const int r   = tid & 127;
        const int kq0 = (tid >> 7) * 4;
#pragma unroll
        for (int i = 0; i < 4; ++i) {
            const int k = kq0 + 8 * i;
#pragma unroll
            for (int j = 0; j < 4; ++j)
                v[4 * i + j] = S[(long)(k + j) * ld + r];
        }
    }
}
template <bool KC>
__device__ __forceinline__ void sts_tile(char* tile, int tid, const float v[16]) {
    if (KC) {
        const int q  = tid & 7;
        const int r0 = tid >> 3;
#pragma unroll
        for (int i = 0; i < 4; ++i) {
            uint4 w;
            w.x = f2tf32(v[4 * i + 0]); w.y = f2tf32(v[4 * i + 1]);
            w.z = f2tf32(v[4 * i + 2]); w.w = f2tf32(v[4 * i + 3]);
            *(uint4*)(tile + swz_off(r0 + 32 * i, q * 16)) = w;
        }
    } else {
        const int r   = tid & 127;
        const int kq0 = (tid >> 7) * 4;
#pragma unroll
        for (int i = 0; i < 4; ++i) {
            const int k = kq0 + 8 * i;
            uint4 w;
            w.x = f2tf32(v[4 * i + 0]); w.y = f2tf32(v[4 * i + 1]);
            w.z = f2tf32(v[4 * i + 2]); w.w = f2tf32(v[4 * i + 3]);
            *(uint4*)(tile + swz_off(r, k * 4)) = w;
        }
    }
}

__device__ __forceinline__ void mma_chunk(uint32_t As, uint32_t Bs,
                                          int wm, int wn, int lane,
                                          float (&acc)[4][4][4]) {
    const int mat  = lane >> 3;
    const int l7   = lane & 7;
    const int arow = (mat & 1) * 8 + l7;
    const int ac16 = (mat >> 1);
    const int brow = (mat >> 1) * 8 + l7;
    const int bc16 = (mat & 1);

    uint32_t abase[4], bbase[2];
#pragma unroll
    for (int mi = 0; mi < 4; ++mi)
        abase[mi] = As + (wm * 64 + mi * 16 + arow) * 128;
#pragma unroll
    for (int bi = 0; bi < 2; ++bi)
        bbase[bi] = Bs + (wn * 32 + bi * 16 + brow) * 128;

#pragma unroll
    for (int ks = 0; ks < 4; ++ks) {
        const uint32_t acol = ((ks * 2 + ac16) ^ l7) << 4;
        const uint32_t bcol = ((ks * 2 + bc16) ^ l7) << 4;
        uint32_t a[4][4];
#pragma unroll
        for (int mi = 0; mi < 4; ++mi)
            LDSM_X4(a[mi][0], a[mi][1], a[mi][2], a[mi][3], abase[mi] + acol);
        uint32_t b[2][4];
#pragma unroll
        for (int bi = 0; bi < 2; ++bi)
            LDSM_X4(b[bi][0], b[bi][1], b[bi][2], b[bi][3], bbase[bi] + bcol);
#pragma unroll
        for (int mi = 0; mi < 4; ++mi)
#pragma unroll
            for (int ni = 0; ni < 4; ++ni)
                MMA_TF32(acc[mi][ni], a[mi],
                         b[ni >> 1][(ni & 1) * 2], b[ni >> 1][(ni & 1) * 2 + 1]);
    }
}

// EPI: 0 = plain f32 store, 1 = store tf32 bits
template <int KT, bool AKC, bool BKC, int EPI>
__device__ __forceinline__ void gemm_body(const float* __restrict__ A, long ldA,
                                          const float* __restrict__ B, long ldB,
                                          float* __restrict__ C, long ldC) {
    extern __shared__ __align__(16) char dyn[];

    const int tid  = threadIdx.x;
    const int wid  = tid >> 5;
    const int lane = tid & 31;
    const int wm   = wid >> 2;
    const int wn   = wid & 3;
    const int m0   = blockIdx.y * 128;
    const int n0   = blockIdx.x * 128;

    const uint32_t dynb = smem_u32(dyn);
    const uint32_t base = (dynb + 127u) & ~127u;
    char* tiles = dyn + (base - dynb);

    float acc[4][4][4] = {};
    float va[16], vb[16];

    auto aptr = [&](long k0) {
        return AKC ? (A + (long)m0 * ldA + k0) : (A + k0 * ldA + m0);
    };
    auto bptr = [&](long k0) {
        return BKC ? (B + (long)n0 * ldB + k0) : (B + k0 * ldB + n0);
    };

    ldg_tile<AKC>(aptr(0), ldA, tid, va);
    ldg_tile<BKC>(bptr(0), ldB, tid, vb);
    sts_tile<AKC>(tiles, tid, va);
    sts_tile<BKC>(tiles + TILE_BYTES, tid, vb);
    __syncthreads();

    const int NIT = KT / BKT;
    if (NIT > 1) {
        ldg_tile<AKC>(aptr(BKT), ldA, tid, va);
        ldg_tile<BKC>(bptr(BKT), ldB, tid, vb);
    }

    for (int it = 0; it < NIT; ++it) {
        const int cur = it & 1;
        if (it + 1 < NIT) {
            char* nxt = tiles + (cur ^ 1) * 2 * TILE_BYTES;
            sts_tile<AKC>(nxt, tid, va);
            sts_tile<BKC>(nxt + TILE_BYTES, tid, vb);
        }
        mma_chunk(base + cur * 2 * TILE_BYTES,
                  base + cur * 2 * TILE_BYTES + TILE_BYTES,
                  wm, wn, lane, acc);
        if (it + 2 < NIT) {
            const long k0 = (long)(it + 2) * BKT;
            ldg_tile<AKC>(aptr(k0), ldA, tid, va);
            ldg_tile<BKC>(bptr(k0), ldB, tid, vb);
        }
        __syncthreads();
    }

#pragma unroll
    for (int mi = 0; mi < 4; ++mi) {
        const int r0 = m0 + wm * 64 + mi * 16 + (lane >> 2);
#pragma unroll
        for (int ni = 0; ni < 4; ++ni) {
            const int c = n0 + wn * 32 + ni * 8 + (lane & 3) * 2;
            float2 v0 = {acc[mi][ni][0], acc[mi][ni][1]};
            float2 v1 = {acc[mi][ni][2], acc[mi][ni][3]};
            if (EPI == 1) {
                v0.x = __uint_as_float(f2tf32(v0.x));
                v0.y = __uint_as_float(f2tf32(v0.y));
                v1.x = __uint_as_float(f2tf32(v1.x));
                v1.y = __uint_as_float(f2tf32(v1.y));
            }
            *(float2*)(C + (long)r0 * ldC + c)       = v0;
            *(float2*)(C + (long)(r0 + 8) * ldC + c) = v1;
        }
    }
}

// ================= cp.async engine (k2 / k3) ==============================
// A: ld 2048, k-contig tf32 bits. B: row stride 512, k-contig tf32 bits
// (optionally expert-segmented via BSEG). CTA 128x256, warp 64x64, 3 stages.
__device__ __forceinline__ void ca_load_stage(uint32_t sbase,
                                              const float* __restrict__ Ak,
                                              const float* __restrict__ Bk,
                                              int tid) {
    const int q  = tid & 7;
    const int r0 = tid >> 3;
#pragma unroll
    for (int i = 0; i < 4; ++i) {          // A: 128 rows x 32 k
        const int r = r0 + 32 * i;
        CP_ASYNC16(sbase + swz16(r, q), (const void*)(Ak + (long)r * 2048 + q * 4));
    }
#pragma unroll
    for (int i = 0; i < 8; ++i) {          // B: 256 rows x 32 k
        const int r = r0 + 32 * i;
        CP_ASYNC16(sbase + 16384 + swz16(r, q),
                   (const void*)(Bk + (long)r * 512 + q * 4));
    }
}

__device__ __forceinline__ void mma_chunk64(uint32_t As, uint32_t Bs,
                                            int wm, int wn, int lane,
                                            float (&acc)[4][8][4]) {
    const int mat  = lane >> 3;
    const int l7   = lane & 7;
    const int arow = (mat & 1) * 8 + l7;
    const int ac16 = (mat >> 1);
    const int brow = (mat >> 1) * 8 + l7;
    const int bc16 = (mat & 1);

    uint32_t abase[4], bbase[4];
#pragma unroll
    for (int mi = 0; mi < 4; ++mi)
        abase[mi] = As + (wm * 64 + mi * 16 + arow) * 128;
#pragma unroll
    for (int bi = 0; bi < 4; ++bi)
        bbase[bi] = Bs + (wn * 64 + bi * 16 + brow) * 128;

#pragma unroll
    for (int ks = 0; ks < 4; ++ks) {
        const uint32_t acol = ((ks * 2 + ac16) ^ l7) << 4;
        const uint32_t bcol = ((ks * 2 + bc16) ^ l7) << 4;
        uint32_t a[4][4];
#pragma unroll
        for (int mi = 0; mi < 4; ++mi)
            LDSM_X4(a[mi][0], a[mi][1], a[mi][2], a[mi][3], abase[mi] + acol);
        uint32_t b[4][4];
#pragma unroll
        for (int bi = 0; bi < 4; ++bi)
            LDSM_X4(b[bi][0], b[bi][1], b[bi][2], b[bi][3], bbase[bi] + bcol);
#pragma unroll
        for (int mi = 0; mi < 4; ++mi)
#pragma unroll
            for (int ni = 0; ni < 8; ++ni)
                MMA_TF32(acc[mi][ni], a[mi],
                         b[ni >> 1][(ni & 1) * 2], b[ni >> 1][(ni & 1) * 2 + 1]);
    }
}

// EPI: 1 = store tf32 bits, 2 = + bias[c]*srow[r], f32 store
template <int KT, int EPI, long long BSEG>
__device__ __forceinline__ void casync_body(const float* __restrict__ A,
                                            const float* __restrict__ B,
                                            const float* __restrict__ bias,
                                            const float* __restrict__ srow,
                                            float* __restrict__ C, long ldC) {
    const int m0   = blockIdx.x * 128;          // m-fastest grid
    const int n0   = blockIdx.y * 256;
    const int tid  = threadIdx.x;
    const int wid  = tid >> 5;
    const int lane = tid & 31;
    const int wm   = wid >> 2;
    const int wn   = wid & 3;

    extern __shared__ __align__(16) char dyn[];
    const uint32_t dynb = smem_u32(dyn);
    const uint32_t base = (dynb + 127u) & ~127u;

    const float* Ab = A + (long)m0 * 2048;
    auto bkp = [&](int k0) {
        return B + (long)(k0 >> 9) * BSEG + (long)n0 * 512 + (k0 & 511);
    };

    float acc[4][8][4] = {};

    ca_load_stage(base, Ab, bkp(0), tid);                   CP_COMMIT();
    ca_load_stage(base + CA_STAGE, Ab + 32, bkp(32), tid);  CP_COMMIT();

    const int NIT = KT / BKT;
    for (int it = 0; it < NIT; ++it) {
        if (it + 2 < NIT) { CP_WAIT(1); } else { CP_WAIT(0); }
        __syncthreads();
        if (it + 2 < NIT) {
            const int k0 = (it + 2) * BKT;
            ca_load_stage(base + ((it + 2) % 3) * CA_STAGE, Ab + k0, bkp(k0), tid);
            CP_COMMIT();
        }
        const uint32_t st = base + (it % 3) * CA_STAGE;
        mma_chunk64(st, st + 16384, wm, wn, lane, acc);
    }

#pragma unroll
    for (int mi = 0; mi < 4; ++mi) {
        const int r = m0 + wm * 64 + mi * 16 + (lane >> 2);
        float s0 = 0.f, s1 = 0.f;
        if (EPI == 2) { s0 = __ldg(srow + r); s1 = __ldg(srow + r + 8); }
        float* row0 = C + (long)r * ldC;
#pragma unroll
        for (int ni = 0; ni < 8; ++ni) {
            const int c = n0 + wn * 64 + ni * 8 + (lane & 3) * 2;
            float2 v0 = {acc[mi][ni][0], acc[mi][ni][1]};
            float2 v1 = {acc[mi][ni][2], acc[mi][ni][3]};
            if (EPI == 2) {
                const float b0 = __ldg(bias + c), b1 = __ldg(bias + c + 1);
                v0.x += b0 * s0; v0.y += b1 * s0;
                v1.x += b0 * s1; v1.y += b1 * s1;
            } else {
                v0.x = __uint_as_float(f2tf32(v0.x));
                v0.y = __uint_as_float(f2tf32(v0.y));
                v1.x = __uint_as_float(f2tf32(v1.x));
                v1.y = __uint_as_float(f2tf32(v1.y));
            }
            *(float2*)(row0 + c)            = v0;
            *(float2*)(row0 + 8 * ldC + c)  = v1;
        }
    }
}

// ---------------------------------------------------------------- kernels --
// k1: xdT[b,e] (i,c) = x_e^T @ dispatch_e  (both mn-contig), tf32-bit store
__global__ __launch_bounds__(NTHREADS, 2)
void k1_dispatch(const float* __restrict__ x, const float* __restrict__ dm) {
    const int bz = blockIdx.z, b = bz >> 2, e = bz & 3;
    gemm_body<1024, false, false, 1>(
        x  + (long)b * 1024 * 2048 + e * 512, 2048,   // A: (k=t, m=i)
        dm + (long)b * 1024 * 2048 + e * 512, 2048,   // B: (k=t, n=c)
        g_xdT + (long)bz * 512 * 512, 512);
}

__global__ __launch_bounds__(256)
void k_rowsum(const float* __restrict__ cmb) {
    const int warp = (blockIdx.x * 256 + threadIdx.x) >> 5;
    const int lane = threadIdx.x & 31;
    if (warp >= 4096) return;
    const float4* p = (const float4*)(cmb + (long)warp * 2048);
    float s = 0.f;
#pragma unroll
    for (int j = 0; j < 16; ++j) {
        const float4 v = p[lane + 32 * j];
        s += (v.x + v.y) + (v.z + v.w);
    }
#pragma unroll
    for (int o = 16; o; o >>= 1) s += __shfl_xor_sync(0xFFFFFFFFu, s, o);
    if (lane == 0) g_s[warp] = s;
}

__global__ __launch_bounds__(256)
void k_wcvt(const float* __restrict__ w) {
    const long i = ((long)blockIdx.x * 256 + threadIdx.x) * 4;
    const float4 v = *(const float4*)(w + i);
    uint4 u;
    u.x = f2tf32(v.x); u.y = f2tf32(v.y); u.z = f2tf32(v.z); u.w = f2tf32(v.w);
    *(uint4*)(g_wt + i) = u;
}
__global__ __launch_bounds__(256)
void k_ccvt(const float* __restrict__ cmb) {
    const long i = ((long)blockIdx.x * 256 + threadIdx.x) * 4;
    const float4 v = *(const float4*)(cmb + i);
    uint4 u;
    u.x = f2tf32(v.x); u.y = f2tf32(v.y); u.z = f2tf32(v.z); u.w = f2tf32(v.w);
    *(uint4*)(g_cz + i) = u;
}

// k2: z_e (1024x512) = cz_e @ xdT_e^T, tf32-bit store  (grid 8 x 2 x 16)
__global__ __launch_bounds__(256, 1)
void k2_z(int dummy) {
    const int bz = blockIdx.z, b = bz >> 2, e = bz & 3;
    casync_body<512, 1, 0>(
        g_cz  + (long)b * 1024 * 2048 + e * 512,      // A (m=t, k=c) ld 2048
        g_xdT + (long)bz * 512 * 512,                 // B (n=i, k=c) rows of 512
        nullptr, nullptr,
        g_z + (long)b * 1024 * 2048 + e * 512, 2048);
}

// k3: out[b] = z[b] @ wt_seg^T + bias*s   (grid 8 x 32 x 4)
__global__ __launch_bounds__(256, 1)
void k3_out(const float* __restrict__ bias, float* __restrict__ out) {
    const int b = blockIdx.z;
    casync_body<2048, 2, 8192ll * 512>(
        g_z + (long)b * 1024 * 2048,
        g_wt,
        bias, g_s + b * 1024,
        out + (long)b * 1024 * 8192, 8192);
}

// ----------------------------------------------------------------- launch --
extern "C" void kernel_launch(void* const* d_in, const int* in_sizes, int n_in,
                              void* d_out, int out_size) {
    const float* x       = (const float*)d_in[0];
    const float* combine = (const float*)d_in[1];
    const float* dmask   = (const float*)d_in[2];
    const float* weight  = (const float*)d_in[3];
    const float* bias    = (const float*)d_in[4];
    float*       out     = (float*)d_out;

    const int SMEM1 = 4 * TILE_BYTES + 256;
    cudaFuncSetAttribute(k1_dispatch, cudaFuncAttributeMaxDynamicSharedMemorySize, SMEM1);
    cudaFuncSetAttribute(k2_z,        cudaFuncAttributeMaxDynamicSharedMemorySize, CA_SMEM);
    cudaFuncSetAttribute(k3_out,      cudaFuncAttributeMaxDynamicSharedMemorySize, CA_SMEM);

    k_wcvt     <<<8192 * 2048 / 1024, 256>>>(weight);
    k_ccvt     <<<4 * 1024 * 2048 / 1024, 256>>>(combine);
    k1_dispatch<<<dim3(4, 4, 16), NTHREADS, SMEM1>>>(x, dmask);
    k_rowsum   <<<512, 256>>>(combine);
    k2_z       <<<dim3(8, 2, 16), 256, CA_SMEM>>>(0);
    k3_out     <<<dim3(8, 32, 4), 256, CA_SMEM>>>(bias, out);
}

// round 16
// speedup vs baseline: 1.1145x; 1.1145x over previous
#include <cuda_runtime.h>
#include <cstdint>

// ---------------------------------------------------------------------------
// ExpertsChooseMaskedExpand — round 16: 2-CTA/SM cp.async engine
//
//   WC : wt  = tf32(weight)                                    (~16 us)
//   CR : cz  = tf32(combine), s = rowsum(combine)  [fused]     (~8 us)
//   K1 : xdT[b,e] (512x512, tf32) = x_e^T @ dispatch_e          (old engine)
//   K2 : z[b] (1024x2048, tf32)   = cz_e @ xdT_e^T              (ca engine)
//   K3 : out[b] (1024x8192)       = z[b] @ wt_seg^T + bias*s    (ca engine)
//
// ca engine: CTA 128x128, 4 warps (64x64 each), 3-stage cp.async pipeline
// (32 KB/stage), __launch_bounds__(128, 2) -> 2 CTAs/SM so syncs/drains of
// one CTA overlap MMA of the other. Operands pre-converted tf32 bits.
// ---------------------------------------------------------------------------

#define NTHREADS   256
#define BKT        32
#define TILE_BYTES 16384            // old engine: 128 rows x 128 B
#define CA_STAGE   32768            // A 16 KB + B 16 KB
#define CA_SMEM    (3 * CA_STAGE + 256)

__device__ float g_xdT[16ull * 512 * 512];    // 16 MB  (b*4+e, i, c) tf32 bits
__device__ float g_cz [4ull * 1024 * 2048];   // 32 MB  combine, tf32 bits
__device__ float g_z  [4ull * 1024 * 2048];   // 32 MB  (b, t, e*512+i) tf32 bits
__device__ float g_wt [8192ull * 2048];       // 64 MB  weight, tf32 bits
__device__ float g_s  [4 * 1024];             // rowsum of combine (f32)

// ---------------------------------------------------------------- helpers --
__device__ __forceinline__ uint32_t smem_u32(const void* p) {
    uint32_t a;
    asm("{ .reg .u64 t; cvta.to.shared.u64 t, %1; cvt.u32.u64 %0, t; }"
        : "=r"(a) : "l"(p));
    return a;
}
__device__ __forceinline__ uint32_t f2tf32(float x) {
    uint32_t r;
    asm("cvt.rna.tf32.f32 %0, %1;" : "=r"(r) : "f"(x));
    return r;
}
__device__ __forceinline__ int swz_off(int row, int byte_in_row) {
    const int c16 = byte_in_row >> 4;
    const int sub = byte_in_row & 15;
    return row * 128 + (((c16 ^ (row & 7)) << 4) | sub);
}
__device__ __forceinline__ uint32_t swz16(int row, int q) {
    return (uint32_t)(row * 128 + ((q ^ (row & 7)) << 4));
}

#define LDSM_X4(r0, r1, r2, r3, addr)                                          \
    asm volatile("ldmatrix.sync.aligned.m8n8.x4.shared.b16 {%0,%1,%2,%3}, [%4];" \
                 : "=r"(r0), "=r"(r1), "=r"(r2), "=r"(r3) : "r"(addr))

#define MMA_TF32(c, a, b0v, b1v)                                               \
    asm volatile("mma.sync.aligned.m16n8k8.row.col.f32.tf32.tf32.f32 "         \
                 "{%0,%1,%2,%3}, {%4,%5,%6,%7}, {%8,%9}, {%0,%1,%2,%3};"       \
                 : "+f"((c)[0]), "+f"((c)[1]), "+f"((c)[2]), "+f"((c)[3])      \
                 : "r"((a)[0]), "r"((a)[1]), "r"((a)[2]), "r"((a)[3]),         \
                   "r"(b0v), "r"(b1v))

#define CP_ASYNC16(dst, src)                                                   \
    asm volatile("cp.async.cg.shared.global [%0], [%1], 16;"                   \
                 :: "r"(dst), "l"(src))
#define CP_COMMIT()  asm volatile("cp.async.commit_group;" ::: "memory")
#define CP_WAIT(n)   asm volatile("cp.async.wait_group %0;" :: "n"(n) : "memory")

// ================= old engine (k1 only) ===================================
template <bool KC>
__device__ __forceinline__ void ldg_tile(const float* __restrict__ S, long ld,
                                         int tid, float v[16]) {
    if (KC) {
        const int q  = tid & 7;
        const int r0 = tid >> 3;
#pragma unroll
        for (int i = 0; i < 4; ++i)
            *(float4*)(v + 4 * i) =
                *(const float4*)(S + (long)(r0 + 32 * i) * ld + q * 4);
    } else {
        const int r   = tid & 127;
        const int kq0 = (tid >> 7) * 4;
#pragma unroll
        for (int i = 0; i < 4; ++i) {
            const int k = kq0 + 8 * i;
#pragma unroll
            for (int j = 0; j < 4; ++j)
                v[4 * i + j] = S[(long)(k + j) * ld + r];
        }
    }
}
template <bool KC>
__device__ __forceinline__ void sts_tile(char* tile, int tid, const float v[16]) {
    if (KC) {
        const int q  = tid & 7;
        const int r0 = tid >> 3;
#pragma unroll
        for (int i = 0; i < 4; ++i) {
            uint4 w;
            w.x = f2tf32(v[4 * i + 0]); w.y = f2tf32(v[4 * i + 1]);
            w.z = f2tf32(v[4 * i + 2]); w.w = f2tf32(v[4 * i + 3]);
            *(uint4*)(tile + swz_off(r0 + 32 * i, q * 16)) = w;
        }
    } else {
        const int r   = tid & 127;
        const int kq0 = (tid >> 7) * 4;
#pragma unroll
        for (int i = 0; i < 4; ++i) {
            const int k = kq0 + 8 * i;
            uint4 w;
            w.x = f2tf32(v[4 * i + 0]); w.y = f2tf32(v[4 * i + 1]);
            w.z = f2tf32(v[4 * i + 2]); w.w = f2tf32(v[4 * i + 3]);
            *(uint4*)(tile + swz_off(r, k * 4)) = w;
        }
    }
}

__device__ __forceinline__ void mma_chunk(uint32_t As, uint32_t Bs,
                                          int wm, int wn, int lane,
                                          float (&acc)[4][4][4]) {
    const int mat  = lane >> 3;
    const int l7   = lane & 7;
    const int arow = (mat & 1) * 8 + l7;
    const int ac16 = (mat >> 1);
    const int brow = (mat >> 1) * 8 + l7;
    const int bc16 = (mat & 1);

    uint32_t abase[4], bbase[2];
#pragma unroll
    for (int mi = 0; mi < 4; ++mi)
        abase[mi] = As + (wm * 64 + mi * 16 + arow) * 128;
#pragma unroll
    for (int bi = 0; bi < 2; ++bi)
        bbase[bi] = Bs + (wn * 32 + bi * 16 + brow) * 128;

#pragma unroll
    for (int ks = 0; ks < 4; ++ks) {
        const uint32_t acol = ((ks * 2 + ac16) ^ l7) << 4;
        const uint32_t bcol = ((ks * 2 + bc16) ^ l7) << 4;
        uint32_t a[4][4];
#pragma unroll
        for (int mi = 0; mi < 4; ++mi)
            LDSM_X4(a[mi][0], a[mi][1], a[mi][2], a[mi][3], abase[mi] + acol);
        uint32_t b[2][4];
#pragma unroll
        for (int bi = 0; bi < 2; ++bi)
            LDSM_X4(b[bi][0], b[bi][1], b[bi][2], b[bi][3], bbase[bi] + bcol);
#pragma unroll
        for (int mi = 0; mi < 4; ++mi)
#pragma unroll
            for (int ni = 0; ni < 4; ++ni)
                MMA_TF32(acc[mi][ni], a[mi],
                         b[ni >> 1][(ni & 1) * 2], b[ni >> 1][(ni & 1) * 2 + 1]);
    }
}

// k1 body: EPI fixed = store tf32 bits
template <int KT, bool AKC, bool BKC>
__device__ __forceinline__ void gemm_body(const float* __restrict__ A, long ldA,
                                          const float* __restrict__ B, long ldB,
                                          float* __restrict__ C, long ldC) {
    extern __shared__ __align__(16) char dyn[];

    const int tid  = threadIdx.x;
    const int wid  = tid >> 5;
    const int lane = tid & 31;
    const int wm   = wid >> 2;
    const int wn   = wid & 3;
    const int m0   = blockIdx.y * 128;
    const int n0   = blockIdx.x * 128;

    const uint32_t dynb = smem_u32(dyn);
    const uint32_t base = (dynb + 127u) & ~127u;
    char* tiles = dyn + (base - dynb);

    float acc[4][4][4] = {};
    float va[16], vb[16];

    auto aptr = [&](long k0) {
        return AKC ? (A + (long)m0 * ldA + k0) : (A + k0 * ldA + m0);
    };
    auto bptr = [&](long k0) {
        return BKC ? (B + (long)n0 * ldB + k0) : (B + k0 * ldB + n0);
    };

    ldg_tile<AKC>(aptr(0), ldA, tid, va);
    ldg_tile<BKC>(bptr(0), ldB, tid, vb);
    sts_tile<AKC>(tiles, tid, va);
    sts_tile<BKC>(tiles + TILE_BYTES, tid, vb);
    __syncthreads();

    const int NIT = KT / BKT;
    if (NIT > 1) {
        ldg_tile<AKC>(aptr(BKT), ldA, tid, va);
        ldg_tile<BKC>(bptr(BKT), ldB, tid, vb);
    }

    for (int it = 0; it < NIT; ++it) {
        const int cur = it & 1;
        if (it + 1 < NIT) {
            char* nxt = tiles + (cur ^ 1) * 2 * TILE_BYTES;
            sts_tile<AKC>(nxt, tid, va);
            sts_tile<BKC>(nxt + TILE_BYTES, tid, vb);
        }
        mma_chunk(base + cur * 2 * TILE_BYTES,
                  base + cur * 2 * TILE_BYTES + TILE_BYTES,
                  wm, wn, lane, acc);
        if (it + 2 < NIT) {
            const long k0 = (long)(it + 2) * BKT;
            ldg_tile<AKC>(aptr(k0), ldA, tid, va);
            ldg_tile<BKC>(bptr(k0), ldB, tid, vb);
        }
        __syncthreads();
    }

#pragma unroll
    for (int mi = 0; mi < 4; ++mi) {
        const int r0 = m0 + wm * 64 + mi * 16 + (lane >> 2);
#pragma unroll
        for (int ni = 0; ni < 4; ++ni) {
            const int c = n0 + wn * 32 + ni * 8 + (lane & 3) * 2;
            float2 v0, v1;
            v0.x = __uint_as_float(f2tf32(acc[mi][ni][0]));
            v0.y = __uint_as_float(f2tf32(acc[mi][ni][1]));
            v1.x = __uint_as_float(f2tf32(acc[mi][ni][2]));
            v1.y = __uint_as_float(f2tf32(acc[mi][ni][3]));
            *(float2*)(C + (long)r0 * ldC + c)       = v0;
            *(float2*)(C + (long)(r0 + 8) * ldC + c) = v1;
        }
    }
}

// ================= ca engine (k2 / k3): CTA 128x128, 4 warps, 2 CTAs/SM ===
__device__ __forceinline__ void ca_load_stage(uint32_t sbase,
                                              const float* __restrict__ Ak,
                                              const float* __restrict__ Bk,
                                              int tid) {
    const int q  = tid & 7;
    const int r0 = tid >> 3;            // 0..15
#pragma unroll
    for (int i = 0; i < 8; ++i) {       // A: 128 rows x 32 k (ld 2048)
        const int r = r0 + 16 * i;
        CP_ASYNC16(sbase + swz16(r, q), (const void*)(Ak + (long)r * 2048 + q * 4));
    }
#pragma unroll
    for (int i = 0; i < 8; ++i) {       // B: 128 rows x 32 k (ld 512)
        const int r = r0 + 16 * i;
        CP_ASYNC16(sbase + 16384 + swz16(r, q),
                   (const void*)(Bk + (long)r * 512 + q * 4));
    }
}

__device__ __forceinline__ void mma_chunk64(uint32_t As, uint32_t Bs,
                                            int wm, int wn, int lane,
                                            float (&acc)[4][8][4]) {
    const int mat  = lane >> 3;
    const int l7   = lane & 7;
    const int arow = (mat & 1) * 8 + l7;
    const int ac16 = (mat >> 1);
    const int brow = (mat >> 1) * 8 + l7;
    const int bc16 = (mat & 1);

    uint32_t abase[4], bbase[4];
#pragma unroll
    for (int mi = 0; mi < 4; ++mi)
        abase[mi] = As + (wm * 64 + mi * 16 + arow) * 128;
#pragma unroll
    for (int bi = 0; bi < 4; ++bi)
        bbase[bi] = Bs + (wn * 64 + bi * 16 + brow) * 128;

#pragma unroll
    for (int ks = 0; ks < 4; ++ks) {
        const uint32_t acol = ((ks * 2 + ac16) ^ l7) << 4;
        const uint32_t bcol = ((ks * 2 + bc16) ^ l7) << 4;
        uint32_t a[4][4];
#pragma unroll
        for (int mi = 0; mi < 4; ++mi)
            LDSM_X4(a[mi][0], a[mi][1], a[mi][2], a[mi][3], abase[mi] + acol);
        uint32_t b[4][4];
#pragma unroll
        for (int bi = 0; bi < 4; ++bi)
            LDSM_X4(b[bi][0], b[bi][1], b[bi][2], b[bi][3], bbase[bi] + bcol);
#pragma unroll
        for (int mi = 0; mi < 4; ++mi)
#pragma unroll
            for (int ni = 0; ni < 8; ++ni)
                MMA_TF32(acc[mi][ni], a[mi],
                         b[ni >> 1][(ni & 1) * 2], b[ni >> 1][(ni & 1) * 2 + 1]);
    }
}

// EPI: 1 = store tf32 bits, 2 = + bias[c]*srow[r], f32 store
template <int KT, int EPI, long long BSEG>
__device__ __forceinline__ void casync_body(const float* __restrict__ A,
                                            const float* __restrict__ B,
                                            const float* __restrict__ bias,
                                            const float* __restrict__ srow,
                                            float* __restrict__ C, long ldC) {
    const int n0   = blockIdx.x * 128;          // n-fastest grid
    const int m0   = blockIdx.y * 128;
    const int tid  = threadIdx.x;
    const int wid  = tid >> 5;                  // 0..3
    const int lane = tid & 31;
    const int wm   = wid >> 1;                  // 0..1
    const int wn   = wid & 1;                   // 0..1

    extern __shared__ __align__(16) char dyn[];
    const uint32_t dynb = smem_u32(dyn);
    const uint32_t base = (dynb + 127u) & ~127u;

    const float* Ab = A + (long)m0 * 2048;
    auto bkp = [&](int k0) {
        return B + (long)(k0 >> 9) * BSEG + (long)n0 * 512 + (k0 & 511);
    };

    float acc[4][8][4] = {};

    ca_load_stage(base, Ab, bkp(0), tid);                   CP_COMMIT();
    ca_load_stage(base + CA_STAGE, Ab + 32, bkp(32), tid);  CP_COMMIT();

    const int NIT = KT / BKT;
    for (int it = 0; it < NIT; ++it) {
        if (it + 2 < NIT) { CP_WAIT(1); } else { CP_WAIT(0); }
        __syncthreads();
        if (it + 2 < NIT) {
            const int k0 = (it + 2) * BKT;
            ca_load_stage(base + ((it + 2) % 3) * CA_STAGE, Ab + k0, bkp(k0), tid);
            CP_COMMIT();
        }
        const uint32_t st = base + (it % 3) * CA_STAGE;
        mma_chunk64(st, st + 16384, wm, wn, lane, acc);
    }

#pragma unroll
    for (int mi = 0; mi < 4; ++mi) {
        const int r = m0 + wm * 64 + mi * 16 + (lane >> 2);
        float s0 = 0.f, s1 = 0.f;
        if (EPI == 2) { s0 = __ldg(srow + r); s1 = __ldg(srow + r + 8); }
        float* row0 = C + (long)r * ldC;
#pragma unroll
        for (int ni = 0; ni < 8; ++ni) {
            const int c = n0 + wn * 64 + ni * 8 + (lane & 3) * 2;
            float2 v0 = {acc[mi][ni][0], acc[mi][ni][1]};
            float2 v1 = {acc[mi][ni][2], acc[mi][ni][3]};
            if (EPI == 2) {
                const float b0 = __ldg(bias + c), b1 = __ldg(bias + c + 1);
                v0.x += b0 * s0; v0.y += b1 * s0;
                v1.x += b0 * s1; v1.y += b1 * s1;
            } else {
                v0.x = __uint_as_float(f2tf32(v0.x));
                v0.y = __uint_as_float(f2tf32(v0.y));
                v1.x = __uint_as_float(f2tf32(v1.x));
                v1.y = __uint_as_float(f2tf32(v1.y));
            }
            *(float2*)(row0 + c)            = v0;
            *(float2*)(row0 + 8 * ldC + c)  = v1;
        }
    }
}

// ---------------------------------------------------------------- kernels --
// k1: xdT[b,e] (i,c) = x_e^T @ dispatch_e  (both mn-contig), tf32-bit store
__global__ __launch_bounds__(NTHREADS, 2)
void k1_dispatch(const float* __restrict__ x, const float* __restrict__ dm) {
    const int bz = blockIdx.z, b = bz >> 2, e = bz & 3;
    gemm_body<1024, false, false>(
        x  + (long)b * 1024 * 2048 + e * 512, 2048,   // A: (k=t, m=i)
        dm + (long)b * 1024 * 2048 + e * 512, 2048,   // B: (k=t, n=c)
        g_xdT + (long)bz * 512 * 512, 512);
}

__global__ __launch_bounds__(256)
void k_wcvt(const float* __restrict__ w) {
    const long i = ((long)blockIdx.x * 256 + threadIdx.x) * 4;
    const float4 v = *(const float4*)(w + i);
    uint4 u;
    u.x = f2tf32(v.x); u.y = f2tf32(v.y); u.z = f2tf32(v.z); u.w = f2tf32(v.w);
    *(uint4*)(g_wt + i) = u;
}

// fused: convert combine row -> tf32 bits AND accumulate rowsum (one pass)
__global__ __launch_bounds__(256)
void k_ccvt_rs(const float* __restrict__ cmb) {
    __shared__ float red[8];
    const int row = blockIdx.x;              // 0..4095 (b*1024 + t)
    const int tid = threadIdx.x;
    const float4* p = (const float4*)(cmb + (long)row * 2048);
    uint4*       o = (uint4*)(g_cz + (long)row * 2048);

    float s = 0.f;
#pragma unroll
    for (int j = 0; j < 2; ++j) {
        const float4 v = p[tid * 2 + j];
        s += (v.x + v.y) + (v.z + v.w);
        uint4 u;
        u.x = f2tf32(v.x); u.y = f2tf32(v.y);
        u.z = f2tf32(v.z); u.w = f2tf32(v.w);
        o[tid * 2 + j] = u;
    }
#pragma unroll
    for (int off = 16; off; off >>= 1) s += __shfl_xor_sync(0xFFFFFFFFu, s, off);
    if ((tid & 31) == 0) red[tid >> 5] = s;
    __syncthreads();
    if (tid < 8) {
        float t = red[tid];
#pragma unroll
        for (int off = 4; off; off >>= 1) t += __shfl_xor_sync(0xFFu, t, off);
        if (tid == 0) g_s[row] = t;
    }
}

// k2: z_e (1024x512) = cz_e @ xdT_e^T, tf32-bit store  (grid 4 x 8 x 16)
__global__ __launch_bounds__(128, 2)
void k2_z(int dummy) {
    const int bz = blockIdx.z, b = bz >> 2, e = bz & 3;
    casync_body<512, 1, 0>(
        g_cz  + (long)b * 1024 * 2048 + e * 512,      // A (m=t, k=c) ld 2048
        g_xdT + (long)bz * 512 * 512,                 // B (n=i, k=c) rows of 512
        nullptr, nullptr,
        g_z + (long)b * 1024 * 2048 + e * 512, 2048);
}

// k3: out[b] = z[b] @ wt_seg^T + bias*s   (grid 64 x 8 x 4)
__global__ __launch_bounds__(128, 2)
void k3_out(const float* __restrict__ bias, float* __restrict__ out) {
    const int b = blockIdx.z;
    casync_body<2048, 2, 8192ll * 512>(
        g_z + (long)b * 1024 * 2048,
        g_wt,
        bias, g_s + b * 1024,
        out + (long)b * 1024 * 8192, 8192);
}

// ----------------------------------------------------------------- launch --
extern "C" void kernel_launch(void* const* d_in, const int* in_sizes, int n_in,
                              void* d_out, int out_size) {
    const float* x       = (const float*)d_in[0];
    const float* combine = (const float*)d_in[1];
    const float* dmask   = (const float*)d_in[2];
    const float* weight  = (const float*)d_in[3];
    const float* bias    = (const float*)d_in[4];
    float*       out     = (float*)d_out;

    const int SMEM1 = 4 * TILE_BYTES + 256;
    cudaFuncSetAttribute(k1_dispatch, cudaFuncAttributeMaxDynamicSharedMemorySize, SMEM1);
    cudaFuncSetAttribute(k2_z,        cudaFuncAttributeMaxDynamicSharedMemorySize, CA_SMEM);
    cudaFuncSetAttribute(k3_out,      cudaFuncAttributeMaxDynamicSharedMemorySize, CA_SMEM);

    k_wcvt     <<<8192 * 2048 / 1024, 256>>>(weight);
    k_ccvt_rs  <<<4096, 256>>>(combine);
    k1_dispatch<<<dim3(4, 4, 16), NTHREADS, SMEM1>>>(x, dmask);
    k2_z       <<<dim3(4, 8, 16), 128, CA_SMEM>>>(0);
    k3_out     <<<dim3(64, 8, 4), 128, CA_SMEM>>>(bias, out);
}